// round 11
// baseline (speedup 1.0000x reference)
#include <cuda_runtime.h>
#include <math.h>

// Pe_i_CrossAttention: fused point-transformer local attention.
// B=4, C=64, N=16384, K=16, H=8, D=8.
// R11: warp = 2 points, lane = (p, kh, h).
//  - W read straight from GLOBAL (pre-permuted [c][quad][h][dd]) via __ldg:
//    each LDG.128 instr covers one 128B line -> 1 wavefront; no smem W, no
//    per-CTA W copy; smem drops 59KB -> 7.4KB -> 4 CTAs/SM (32 warps).
//  - No per-c shuffles: full 8-dim r-dot in-lane; o[8] accumulated in-lane
//    over own k-half, one 8-shfl combine at the end.
// energy[h,k] = (Wk_h^T q_h).nb_k ; out[h] = Wv_h @ (sum_k attn_k nb_k)

#define B_      4
#define C_      64
#define N_      16384
#define K_      16
#define CP3     67
#define PTS     16                  // points per CTA (8 warps x 2)
#define THREADS 256
#define PC_STRIDE 68
#define SX_STRIDE 48
#define W_ELEMS (CP3 * C_)          // 4288
#define CSTR    ((size_t)N_ * K_)   // float stride between c-rows of neighbors

__device__ __align__(16) float g_WT[3 * W_ELEMS];

// Permute weights once: WT[c*64 + j*32 + h*4 + dd] = W[(h*8 + j*4 + dd)*67 + c]
// -> a warp's 8 heads reading quad j of row c touch one 128B line.
// 1/sqrt(D) folded into Wq.
__global__ void permute_w_kernel(const float* __restrict__ Wq,
                                 const float* __restrict__ Wk,
                                 const float* __restrict__ Wv)
{
    int e = blockIdx.x * blockDim.x + threadIdx.x;
    if (e >= W_ELEMS) return;
    int c  = e >> 6;
    int t  = e & 63;
    int j  = t >> 5;            // quad (dims j*4..j*4+3)
    int h  = (t >> 2) & 7;
    int dd = t & 3;
    int o  = h * 8 + j * 4 + dd;
    g_WT[e]               = Wq[o * CP3 + c] * 0.35355339059327373f;
    g_WT[W_ELEMS + e]     = Wk[o * CP3 + c];
    g_WT[2 * W_ELEMS + e] = Wv[o * CP3 + c];
}

__device__ __forceinline__ float4 ldg4(const float* p) {
    return __ldg((const float4*)p);
}

__global__ __launch_bounds__(THREADS, 4)
void pt_attn_kernel(const float* __restrict__ pcd,
                    const float* __restrict__ neighbors,
                    const float* __restrict__ xyz,
                    const int*   __restrict__ idx_all,
                    float*       __restrict__ out)
{
    __shared__ float pc[PTS * PC_STRIDE];     // [16][68] center features
    __shared__ float sxyz[PTS * SX_STRIDE];   // [16][3][16] gathered rel-xyz

    const int tid = threadIdx.x;
    const int g0  = blockIdx.x * PTS;         // 16 | 16384 -> never crosses batch
    const int b   = g0 / N_;
    const int n0  = g0 % N_;

    // ---- center features: pc[p][c], coalesced over p (16-wide)
    for (int e = tid; e < C_ * PTS; e += THREADS) {
        int c = e >> 4, p = e & 15;
        pc[p * PC_STRIDE + c] = pcd[(b * C_ + c) * N_ + n0 + p];
    }
    for (int e = tid; e < 3 * PTS; e += THREADS) {
        int j = e >> 4, p = e & 15;
        pc[p * PC_STRIDE + 64 + j] = xyz[(b * 3 + j) * N_ + n0 + p];
    }
    // ---- gathered xyz rows (xyz is 768 KB -> L2-resident)
    for (int e = tid; e < PTS * K_; e += THREADS) {
        int p = e >> 4, k = e & 15;
        int idx = idx_all[(b * N_ + n0 + p) * K_ + k];
        #pragma unroll
        for (int j = 0; j < 3; j++)
            sxyz[p * SX_STRIDE + j * 16 + k] = xyz[(b * 3 + j) * N_ + idx];
    }
    __syncthreads();

    // ---- lane mapping: warp = 2 points
    const int lane = tid & 31;
    const int w    = tid >> 5;
    const int psub = lane & 1;
    const int kh   = (lane >> 1) & 1;         // which 8-k half (for nb/e ownership)
    const int h    = lane >> 2;               // head
    const int pidx = w * 2 + psub;
    const int n    = n0 + pidx;
    const int hq   = h * 4;                   // within-quad W offset for this head
    const float* pcp = pc + pidx * PC_STRIDE;
    const float* sxp = sxyz + pidx * SX_STRIDE + kh * 8;
    const float* nbg = neighbors + ((size_t)(b * C_) * N_ + (size_t)n) * K_ + kh * 8;
    const float* WqT = g_WT;
    const float* WkT = g_WT + W_ELEMS;
    const float* WvT = g_WT + 2 * W_ELEMS;

    // ======== pass 1: full q[8] for (p,h); scale pre-folded ========
    float q[8];
    #pragma unroll
    for (int d = 0; d < 8; d++) q[d] = 0.f;
    #pragma unroll 4
    for (int c = 0; c < CP3; c++) {
        float x = pcp[c];
        float4 w0 = ldg4(WqT + c * 64 + hq);        // dims 0..3, one 128B line/warp
        float4 w1 = ldg4(WqT + c * 64 + 32 + hq);   // dims 4..7
        q[0] = fmaf(w0.x, x, q[0]); q[1] = fmaf(w0.y, x, q[1]);
        q[2] = fmaf(w0.z, x, q[2]); q[3] = fmaf(w0.w, x, q[3]);
        q[4] = fmaf(w1.x, x, q[4]); q[5] = fmaf(w1.y, x, q[5]);
        q[6] = fmaf(w1.z, x, q[6]); q[7] = fmaf(w1.w, x, q[7]);
    }

    // ======== pass 2: energy over own 8 k; full r-dot in-lane (no shfl) ====
    float e0[8];
    #pragma unroll
    for (int k = 0; k < 8; k++) e0[k] = 0.f;
    #pragma unroll 4
    for (int c = 0; c < C_; c++) {
        const float* nr = nbg + (size_t)c * CSTR;
        float4 na  = *(const float4*)nr;
        float4 nb4 = *(const float4*)(nr + 4);
        float4 w0 = ldg4(WkT + c * 64 + hq);
        float4 w1 = ldg4(WkT + c * 64 + 32 + hq);
        float ra = fmaf(w0.x, q[0], w0.y * q[1]);
        float rb = fmaf(w0.z, q[2], w0.w * q[3]);
        ra = fmaf(w1.x, q[4], ra); rb = fmaf(w1.y, q[5], rb);
        ra = fmaf(w1.z, q[6], ra); rb = fmaf(w1.w, q[7], rb);
        float r = ra + rb;
        e0[0] = fmaf(r, na.x, e0[0]);  e0[1] = fmaf(r, na.y, e0[1]);
        e0[2] = fmaf(r, na.z, e0[2]);  e0[3] = fmaf(r, na.w, e0[3]);
        e0[4] = fmaf(r, nb4.x, e0[4]); e0[5] = fmaf(r, nb4.y, e0[5]);
        e0[6] = fmaf(r, nb4.z, e0[6]); e0[7] = fmaf(r, nb4.w, e0[7]);
    }
    #pragma unroll
    for (int j = 0; j < 3; j++) {              // xyz tail rows from smem
        int c = C_ + j;
        float4 na  = *(const float4*)(sxp + j * 16);
        float4 nb4 = *(const float4*)(sxp + j * 16 + 4);
        float4 w0 = ldg4(WkT + c * 64 + hq);
        float4 w1 = ldg4(WkT + c * 64 + 32 + hq);
        float ra = fmaf(w0.x, q[0], w0.y * q[1]);
        float rb = fmaf(w0.z, q[2], w0.w * q[3]);
        ra = fmaf(w1.x, q[4], ra); rb = fmaf(w1.y, q[5], rb);
        ra = fmaf(w1.z, q[6], ra); rb = fmaf(w1.w, q[7], rb);
        float r = ra + rb;
        e0[0] = fmaf(r, na.x, e0[0]);  e0[1] = fmaf(r, na.y, e0[1]);
        e0[2] = fmaf(r, na.z, e0[2]);  e0[3] = fmaf(r, na.w, e0[3]);
        e0[4] = fmaf(r, nb4.x, e0[4]); e0[5] = fmaf(r, nb4.y, e0[5]);
        e0[6] = fmaf(r, nb4.z, e0[6]); e0[7] = fmaf(r, nb4.w, e0[7]);
    }

    // ======== softmax over 16 k (8 local + partner half) ========
    float m = e0[0];
    #pragma unroll
    for (int k = 1; k < 8; k++) m = fmaxf(m, e0[k]);
    m = fmaxf(m, __shfl_xor_sync(0xffffffffu, m, 2));
    float ssum = 0.f;
    #pragma unroll
    for (int k = 0; k < 8; k++) { e0[k] = __expf(e0[k] - m); ssum += e0[k]; }
    ssum += __shfl_xor_sync(0xffffffffu, ssum, 2);
    float inv = 1.f / ssum;
    #pragma unroll
    for (int k = 0; k < 8; k++) e0[k] *= inv;

    // ======== pass 3: o[0..7] += Wv[c, h, :] * s_partial (own k-half) ======
    float o[8];
    #pragma unroll
    for (int d = 0; d < 8; d++) o[d] = 0.f;
    #pragma unroll 4
    for (int c = 0; c < C_; c++) {
        const float* nr = nbg + (size_t)c * CSTR;
        float4 na  = *(const float4*)nr;
        float4 nb4 = *(const float4*)(nr + 4);
        float sa = fmaf(e0[0], na.x, e0[1] * na.y);
        float sb = fmaf(e0[2], na.z, e0[3] * na.w);
        sa = fmaf(e0[4], nb4.x, sa); sb = fmaf(e0[5], nb4.y, sb);
        sa = fmaf(e0[6], nb4.z, sa); sb = fmaf(e0[7], nb4.w, sb);
        float s = sa + sb;
        float4 w0 = ldg4(WvT + c * 64 + hq);
        float4 w1 = ldg4(WvT + c * 64 + 32 + hq);
        o[0] = fmaf(w0.x, s, o[0]); o[1] = fmaf(w0.y, s, o[1]);
        o[2] = fmaf(w0.z, s, o[2]); o[3] = fmaf(w0.w, s, o[3]);
        o[4] = fmaf(w1.x, s, o[4]); o[5] = fmaf(w1.y, s, o[5]);
        o[6] = fmaf(w1.z, s, o[6]); o[7] = fmaf(w1.w, s, o[7]);
    }
    #pragma unroll
    for (int j = 0; j < 3; j++) {
        int c = C_ + j;
        float4 na  = *(const float4*)(sxp + j * 16);
        float4 nb4 = *(const float4*)(sxp + j * 16 + 4);
        float sa = fmaf(e0[0], na.x, e0[1] * na.y);
        float sb = fmaf(e0[2], na.z, e0[3] * na.w);
        sa = fmaf(e0[4], nb4.x, sa); sb = fmaf(e0[5], nb4.y, sb);
        sa = fmaf(e0[6], nb4.z, sa); sb = fmaf(e0[7], nb4.w, sb);
        float s = sa + sb;
        float4 w0 = ldg4(WvT + c * 64 + hq);
        float4 w1 = ldg4(WvT + c * 64 + 32 + hq);
        o[0] = fmaf(w0.x, s, o[0]); o[1] = fmaf(w0.y, s, o[1]);
        o[2] = fmaf(w0.z, s, o[2]); o[3] = fmaf(w0.w, s, o[3]);
        o[4] = fmaf(w1.x, s, o[4]); o[5] = fmaf(w1.y, s, o[5]);
        o[6] = fmaf(w1.z, s, o[6]); o[7] = fmaf(w1.w, s, o[7]);
    }

    // ---- combine kh halves once (partner holds other k-half's contribution)
    #pragma unroll
    for (int d = 0; d < 8; d++)
        o[d] += __shfl_xor_sync(0xffffffffu, o[d], 2);

    // ---- store own quad: dims h*8 + kh*4 + (0..3)
    float* ob = out + ((size_t)(b * C_ + h * 8 + kh * 4)) * N_ + n;
    ob[0]      = o[kh * 4 + 0];
    ob[N_]     = o[kh * 4 + 1];
    ob[2 * N_] = o[kh * 4 + 2];
    ob[3 * N_] = o[kh * 4 + 3];
}

extern "C" void kernel_launch(void* const* d_in, const int* in_sizes, int n_in,
                              void* d_out, int out_size)
{
    (void)in_sizes; (void)n_in; (void)out_size;
    const float* pcd       = (const float*)d_in[0];
    const float* neighbors = (const float*)d_in[1];
    const float* xyz       = (const float*)d_in[2];
    const float* Wq        = (const float*)d_in[3];
    const float* Wk        = (const float*)d_in[4];
    const float* Wv        = (const float*)d_in[5];
    const int*   idx_all   = (const int*)d_in[6];
    float* out = (float*)d_out;

    permute_w_kernel<<<(W_ELEMS + 255) / 256, 256>>>(Wq, Wk, Wv);

    const int grid = (B_ * N_) / PTS;   // 4096
    pt_attn_kernel<<<grid, THREADS>>>(pcd, neighbors, xyz, idx_all, out);
}

// round 12
// speedup vs baseline: 1.0461x; 1.0461x over previous
#include <cuda_runtime.h>
#include <math.h>

// Pe_i_CrossAttention: fused point-transformer local attention.
// B=4, C=64, N=16384, K=16, H=8, D=8.
// R12: warp = 4 points, lane = (p, h). Each lane owns one (point, head)
// COMPLETELY: full q[8], full r-dot, all 16 energies, in-lane softmax,
// full o[8]. Zero FMA duplication (938 FMA/pt = algebraic minimum),
// zero per-c shuffles. W in smem as [c][h*8+d] -> one 128B wavefront
// per LDS.128. nb rows read from global (L2-resident on re-read).
// energy[h,k] = (Wk_h^T q_h).nb_k ; out[h] = Wv_h @ (sum_k attn_k nb_k)

#define B_      4
#define C_      64
#define N_      16384
#define K_      16
#define CP3     67
#define PTS     16                  // points per CTA (8 warps x 4... wait: 8 warps * 4 pts = 32)
#define THREADS 256
#define PC_STRIDE 68
#define SX_STRIDE 52
#define W_ELEMS (CP3 * C_)          // 4288
#define CSTR    ((size_t)N_ * K_)   // float stride between c-rows of neighbors

// NOTE: 8 warps x 4 points = 32 points per CTA.
#undef PTS
#define PTS 32

__device__ __align__(16) float g_WT[3 * W_ELEMS];

// Transpose weights once: WT[c*64 + o] = W[o*67 + c], o = h*8 + d.
// 1/sqrt(D) folded into Wq.
__global__ void permute_w_kernel(const float* __restrict__ Wq,
                                 const float* __restrict__ Wk,
                                 const float* __restrict__ Wv)
{
    int e = blockIdx.x * blockDim.x + threadIdx.x;
    if (e >= W_ELEMS) return;
    int c = e >> 6;
    int o = e & 63;
    g_WT[e]               = Wq[o * CP3 + c] * 0.35355339059327373f;
    g_WT[W_ELEMS + e]     = Wk[o * CP3 + c];
    g_WT[2 * W_ELEMS + e] = Wv[o * CP3 + c];
}

__global__ __launch_bounds__(THREADS, 3)
void pt_attn_kernel(const float* __restrict__ pcd,
                    const float* __restrict__ neighbors,
                    const float* __restrict__ xyz,
                    const int*   __restrict__ idx_all,
                    float*       __restrict__ out)
{
    __shared__ __align__(16) float sW[3 * W_ELEMS];          // 51456 B
    __shared__ float pc[PTS * PC_STRIDE];                    // [32][68]
    __shared__ __align__(16) float sxyz[PTS * SX_STRIDE];    // [32][52] (3x16 used)

    const int tid = threadIdx.x;
    const int g0  = blockIdx.x * PTS;         // 32 | 16384 -> never crosses batch
    const int b   = g0 / N_;
    const int n0  = g0 % N_;

    // ---- W: coalesced float4 copy from pre-transposed global scratch
    {
        const float4* src = (const float4*)g_WT;
        float4*       dst = (float4*)sW;
        for (int e = tid; e < 3 * W_ELEMS / 4; e += THREADS) dst[e] = src[e];
    }
    // ---- center features: pc[p][c], coalesced over p (32-wide)
    for (int e = tid; e < C_ * PTS; e += THREADS) {
        int c = e >> 5, p = e & 31;
        pc[p * PC_STRIDE + c] = pcd[(b * C_ + c) * N_ + n0 + p];
    }
    for (int e = tid; e < 3 * PTS; e += THREADS) {
        int j = e >> 5, p = e & 31;
        pc[p * PC_STRIDE + 64 + j] = xyz[(b * 3 + j) * N_ + n0 + p];
    }
    // ---- gathered xyz rows (xyz is 768 KB -> L2-resident)
    for (int e = tid; e < PTS * K_; e += THREADS) {
        int p = e >> 4, k = e & 15;
        int idx = idx_all[(b * N_ + n0 + p) * K_ + k];
        #pragma unroll
        for (int j = 0; j < 3; j++)
            sxyz[p * SX_STRIDE + j * 16 + k] = xyz[(b * 3 + j) * N_ + idx];
    }
    __syncthreads();

    // ---- lane mapping: warp = 4 points, lane = (p, h)
    const int lane = tid & 31;
    const int w    = tid >> 5;
    const int p    = lane >> 3;               // 0..3
    const int h    = lane & 7;                // head
    const int pidx = w * 4 + p;
    const int n    = n0 + pidx;
    const int ho   = h * 8;                   // W row offset (dims h*8..h*8+7)
    const float* pcp = pc + pidx * PC_STRIDE;
    const float4* sxp = (const float4*)(sxyz + pidx * SX_STRIDE);
    const float* nbg = neighbors + ((size_t)(b * C_) * N_ + (size_t)n) * K_;
    const float4* WqT = (const float4*)sW;                    // [c][16] float4
    const float4* WkT = (const float4*)(sW + W_ELEMS);
    const float4* WvT = (const float4*)(sW + 2 * W_ELEMS);
    const int h2 = h * 2;

    // ======== pass 1: full q[8] (scale pre-folded) ========
    float q[8];
    #pragma unroll
    for (int d = 0; d < 8; d++) q[d] = 0.f;
    #pragma unroll 4
    for (int c = 0; c < CP3; c++) {
        float x = pcp[c];
        float4 w0 = WqT[c * 16 + h2];         // 8 unique float4 -> 1 wavefront
        float4 w1 = WqT[c * 16 + h2 + 1];
        q[0] = fmaf(w0.x, x, q[0]); q[1] = fmaf(w0.y, x, q[1]);
        q[2] = fmaf(w0.z, x, q[2]); q[3] = fmaf(w0.w, x, q[3]);
        q[4] = fmaf(w1.x, x, q[4]); q[5] = fmaf(w1.y, x, q[5]);
        q[6] = fmaf(w1.z, x, q[6]); q[7] = fmaf(w1.w, x, q[7]);
    }

    // ======== pass 2: all 16 energies, full r-dot in-lane ========
    float e0[16];
    #pragma unroll
    for (int k = 0; k < 16; k++) e0[k] = 0.f;
    #pragma unroll 2
    for (int c = 0; c < C_; c++) {
        const float4* nr = (const float4*)(nbg + (size_t)c * CSTR);
        float4 n0v = nr[0], n1v = nr[1], n2v = nr[2], n3v = nr[3];
        float4 w0 = WkT[c * 16 + h2];
        float4 w1 = WkT[c * 16 + h2 + 1];
        float ra = fmaf(w0.x, q[0], w0.y * q[1]);
        float rb = fmaf(w0.z, q[2], w0.w * q[3]);
        ra = fmaf(w1.x, q[4], ra); rb = fmaf(w1.y, q[5], rb);
        ra = fmaf(w1.z, q[6], ra); rb = fmaf(w1.w, q[7], rb);
        float r = ra + rb;
        e0[0]  = fmaf(r, n0v.x, e0[0]);  e0[1]  = fmaf(r, n0v.y, e0[1]);
        e0[2]  = fmaf(r, n0v.z, e0[2]);  e0[3]  = fmaf(r, n0v.w, e0[3]);
        e0[4]  = fmaf(r, n1v.x, e0[4]);  e0[5]  = fmaf(r, n1v.y, e0[5]);
        e0[6]  = fmaf(r, n1v.z, e0[6]);  e0[7]  = fmaf(r, n1v.w, e0[7]);
        e0[8]  = fmaf(r, n2v.x, e0[8]);  e0[9]  = fmaf(r, n2v.y, e0[9]);
        e0[10] = fmaf(r, n2v.z, e0[10]); e0[11] = fmaf(r, n2v.w, e0[11]);
        e0[12] = fmaf(r, n3v.x, e0[12]); e0[13] = fmaf(r, n3v.y, e0[13]);
        e0[14] = fmaf(r, n3v.z, e0[14]); e0[15] = fmaf(r, n3v.w, e0[15]);
    }
    #pragma unroll
    for (int j = 0; j < 3; j++) {             // xyz tail rows from smem
        int c = C_ + j;
        float4 n0v = sxp[j * 4], n1v = sxp[j * 4 + 1];
        float4 n2v = sxp[j * 4 + 2], n3v = sxp[j * 4 + 3];
        float4 w0 = WkT[c * 16 + h2];
        float4 w1 = WkT[c * 16 + h2 + 1];
        float ra = fmaf(w0.x, q[0], w0.y * q[1]);
        float rb = fmaf(w0.z, q[2], w0.w * q[3]);
        ra = fmaf(w1.x, q[4], ra); rb = fmaf(w1.y, q[5], rb);
        ra = fmaf(w1.z, q[6], ra); rb = fmaf(w1.w, q[7], rb);
        float r = ra + rb;
        e0[0]  = fmaf(r, n0v.x, e0[0]);  e0[1]  = fmaf(r, n0v.y, e0[1]);
        e0[2]  = fmaf(r, n0v.z, e0[2]);  e0[3]  = fmaf(r, n0v.w, e0[3]);
        e0[4]  = fmaf(r, n1v.x, e0[4]);  e0[5]  = fmaf(r, n1v.y, e0[5]);
        e0[6]  = fmaf(r, n1v.z, e0[6]);  e0[7]  = fmaf(r, n1v.w, e0[7]);
        e0[8]  = fmaf(r, n2v.x, e0[8]);  e0[9]  = fmaf(r, n2v.y, e0[9]);
        e0[10] = fmaf(r, n2v.z, e0[10]); e0[11] = fmaf(r, n2v.w, e0[11]);
        e0[12] = fmaf(r, n3v.x, e0[12]); e0[13] = fmaf(r, n3v.y, e0[13]);
        e0[14] = fmaf(r, n3v.z, e0[14]); e0[15] = fmaf(r, n3v.w, e0[15]);
    }

    // ======== softmax over 16 k, fully in-lane ========
    float m = e0[0];
    #pragma unroll
    for (int k = 1; k < 16; k++) m = fmaxf(m, e0[k]);
    float ssum = 0.f;
    #pragma unroll
    for (int k = 0; k < 16; k++) { e0[k] = __expf(e0[k] - m); ssum += e0[k]; }
    float inv = 1.f / ssum;
    #pragma unroll
    for (int k = 0; k < 16; k++) e0[k] *= inv;

    // ======== pass 3: o[0..7] += Wv[c,h,:] * (attn . nb[c,:]) ========
    float o[8];
    #pragma unroll
    for (int d = 0; d < 8; d++) o[d] = 0.f;
    #pragma unroll 2
    for (int c = 0; c < C_; c++) {
        const float4* nr = (const float4*)(nbg + (size_t)c * CSTR);
        float4 n0v = nr[0], n1v = nr[1], n2v = nr[2], n3v = nr[3];
        float sa = fmaf(e0[0],  n0v.x, e0[1]  * n0v.y);
        float sb = fmaf(e0[2],  n0v.z, e0[3]  * n0v.w);
        float sc2 = fmaf(e0[4], n1v.x, e0[5]  * n1v.y);
        float sd = fmaf(e0[6],  n1v.z, e0[7]  * n1v.w);
        sa = fmaf(e0[8],  n2v.x, sa); sb = fmaf(e0[9],  n2v.y, sb);
        sc2 = fmaf(e0[10], n2v.z, sc2); sd = fmaf(e0[11], n2v.w, sd);
        sa = fmaf(e0[12], n3v.x, sa); sb = fmaf(e0[13], n3v.y, sb);
        sc2 = fmaf(e0[14], n3v.z, sc2); sd = fmaf(e0[15], n3v.w, sd);
        float s = (sa + sb) + (sc2 + sd);
        float4 w0 = WvT[c * 16 + h2];
        float4 w1 = WvT[c * 16 + h2 + 1];
        o[0] = fmaf(w0.x, s, o[0]); o[1] = fmaf(w0.y, s, o[1]);
        o[2] = fmaf(w0.z, s, o[2]); o[3] = fmaf(w0.w, s, o[3]);
        o[4] = fmaf(w1.x, s, o[4]); o[5] = fmaf(w1.y, s, o[5]);
        o[6] = fmaf(w1.z, s, o[6]); o[7] = fmaf(w1.w, s, o[7]);
    }
    #pragma unroll
    for (int j = 0; j < 3; j++) {
        int c = C_ + j;
        float4 n0v = sxp[j * 4], n1v = sxp[j * 4 + 1];
        float4 n2v = sxp[j * 4 + 2], n3v = sxp[j * 4 + 3];
        float sa = fmaf(e0[0],  n0v.x, e0[1]  * n0v.y);
        float sb = fmaf(e0[2],  n0v.z, e0[3]  * n0v.w);
        float sc2 = fmaf(e0[4], n1v.x, e0[5]  * n1v.y);
        float sd = fmaf(e0[6],  n1v.z, e0[7]  * n1v.w);
        sa = fmaf(e0[8],  n2v.x, sa); sb = fmaf(e0[9],  n2v.y, sb);
        sc2 = fmaf(e0[10], n2v.z, sc2); sd = fmaf(e0[11], n2v.w, sd);
        sa = fmaf(e0[12], n3v.x, sa); sb = fmaf(e0[13], n3v.y, sb);
        sc2 = fmaf(e0[14], n3v.z, sc2); sd = fmaf(e0[15], n3v.w, sd);
        float s = (sa + sb) + (sc2 + sd);
        float4 w0 = WvT[c * 16 + h2];
        float4 w1 = WvT[c * 16 + h2 + 1];
        o[0] = fmaf(w0.x, s, o[0]); o[1] = fmaf(w0.y, s, o[1]);
        o[2] = fmaf(w0.z, s, o[2]); o[3] = fmaf(w0.w, s, o[3]);
        o[4] = fmaf(w1.x, s, o[4]); o[5] = fmaf(w1.y, s, o[5]);
        o[6] = fmaf(w1.z, s, o[6]); o[7] = fmaf(w1.w, s, o[7]);
    }

    // ---- store: out[b, h*8+d, n]
    float* ob = out + ((size_t)(b * C_ + ho)) * N_ + n;
    #pragma unroll
    for (int d = 0; d < 8; d++) ob[(size_t)d * N_] = o[d];
}

extern "C" void kernel_launch(void* const* d_in, const int* in_sizes, int n_in,
                              void* d_out, int out_size)
{
    (void)in_sizes; (void)n_in; (void)out_size;
    const float* pcd       = (const float*)d_in[0];
    const float* neighbors = (const float*)d_in[1];
    const float* xyz       = (const float*)d_in[2];
    const float* Wq        = (const float*)d_in[3];
    const float* Wk        = (const float*)d_in[4];
    const float* Wv        = (const float*)d_in[5];
    const int*   idx_all   = (const int*)d_in[6];
    float* out = (float*)d_out;

    permute_w_kernel<<<(W_ELEMS + 255) / 256, 256>>>(Wq, Wk, Wv);

    const int grid = (B_ * N_) / PTS;   // 2048
    pt_attn_kernel<<<grid, THREADS>>>(pcd, neighbors, xyz, idx_all, out);
}

// round 13
// speedup vs baseline: 1.5087x; 1.4423x over previous
#include <cuda_runtime.h>
#include <math.h>

// Pe_i_CrossAttention: fused point-transformer local attention.
// B=4, C=64, N=16384, K=16, H=8, D=8.
// R13: warp = 4 points, lane = (p, kh, hh).
//   Lane owns k-half kh (8 nbrs) for head-pair {2hh, 2hh+1} and d-half kh.
//   - nb: 2 LDG.128/c/warp (R10-parity 1 wf/pt), amortized over 4 pts
//   - W: quad-permuted smem layout -> each LDS.128 reads ONE 128B line
//     (2 wf/c/warp = 0.5/pt, half of R10); prologue amortized over 32 pts
//   - r/s: 4-dim partial per head in-lane + one shfl_xor(4) -> no FMA dup
// energy[h,k] = (Wk_h^T q_h).nb_k ; out[h] = Wv_h @ (sum_k attn_k nb_k)

#define B_      4
#define C_      64
#define N_      16384
#define K_      16
#define CP3     67
#define PTS     32                  // 8 warps x 4 points
#define THREADS 256
#define PC_STRIDE 68
#define SX_STRIDE 52
#define W_ELEMS (CP3 * C_)          // 4288
#define CSTR    ((size_t)N_ * K_)   // float stride between c-rows of neighbors

__device__ __align__(16) float g_WT[3 * W_ELEMS];

// Quad-permuted transpose:
//   source element: W[o*67 + c], o = h*8 + d;  qidx = h*2 + (d>>2), dd = d&3
//   dest: [c][new_pos][dd], new_pos = (h&1)*8 + (h>>1)*2 + (d>>2)
// -> in-kernel instr j (head 2hh+j) reads float4 at c*16 + j*8 + hh*2 + kh:
//    8 unique float4 per instr, contiguous 128B -> 1 conflict-free wavefront.
// 1/sqrt(D) folded into Wq.
__global__ void permute_w_kernel(const float* __restrict__ Wq,
                                 const float* __restrict__ Wk,
                                 const float* __restrict__ Wv)
{
    int e = blockIdx.x * blockDim.x + threadIdx.x;
    if (e >= W_ELEMS) return;
    int c    = e >> 6;
    int t    = e & 63;
    int qidx = t >> 2;              // 0..15
    int dd   = t & 3;
    int h    = qidx >> 1;
    int kh   = qidx & 1;
    int o    = h * 8 + kh * 4 + dd;
    int np   = (h & 1) * 8 + (h >> 1) * 2 + kh;
    int dst  = c * 64 + np * 4 + dd;
    g_WT[dst]               = Wq[o * CP3 + c] * 0.35355339059327373f;
    g_WT[W_ELEMS + dst]     = Wk[o * CP3 + c];
    g_WT[2 * W_ELEMS + dst] = Wv[o * CP3 + c];
}

__global__ __launch_bounds__(THREADS, 3)
void pt_attn_kernel(const float* __restrict__ pcd,
                    const float* __restrict__ neighbors,
                    const float* __restrict__ xyz,
                    const int*   __restrict__ idx_all,
                    float*       __restrict__ out)
{
    __shared__ __align__(16) float sW[3 * W_ELEMS];          // 51456 B
    __shared__ float pc[PTS * PC_STRIDE];                    // [32][68]
    __shared__ __align__(16) float sxyz[PTS * SX_STRIDE];    // [32][52] (3x16 used)

    const int tid = threadIdx.x;
    const int g0  = blockIdx.x * PTS;         // 32 | 16384 -> never crosses batch
    const int b   = g0 / N_;
    const int n0  = g0 % N_;

    // ---- W: coalesced float4 copy from pre-permuted global scratch
    {
        const float4* src = (const float4*)g_WT;
        float4*       dst = (float4*)sW;
        for (int e = tid; e < 3 * W_ELEMS / 4; e += THREADS) dst[e] = src[e];
    }
    // ---- center features (coalesced over p, 32-wide)
    for (int e = tid; e < C_ * PTS; e += THREADS) {
        int c = e >> 5, p = e & 31;
        pc[p * PC_STRIDE + c] = pcd[(b * C_ + c) * N_ + n0 + p];
    }
    for (int e = tid; e < 3 * PTS; e += THREADS) {
        int j = e >> 5, p = e & 31;
        pc[p * PC_STRIDE + 64 + j] = xyz[(b * 3 + j) * N_ + n0 + p];
    }
    // ---- gathered xyz rows (xyz is 768 KB -> L2-resident)
    for (int e = tid; e < PTS * K_; e += THREADS) {
        int p = e >> 4, k = e & 15;
        int idx = idx_all[(b * N_ + n0 + p) * K_ + k];
        #pragma unroll
        for (int j = 0; j < 3; j++)
            sxyz[p * SX_STRIDE + j * 16 + k] = xyz[(b * 3 + j) * N_ + idx];
    }
    __syncthreads();

    // ---- lane mapping
    const int lane = tid & 31;
    const int w    = tid >> 5;
    const int p    = lane >> 3;               // point within warp (0..3)
    const int kh   = (lane >> 2) & 1;         // k-half / d-half
    const int hh   = lane & 3;                // head-pair index
    const int pidx = w * 4 + p;
    const int n    = n0 + pidx;
    const int wb   = hh * 2 + kh;             // W float4 sub-offset
    const float*  pcp = pc + pidx * PC_STRIDE;
    const float4* sxp = (const float4*)(sxyz + pidx * SX_STRIDE + kh * 8);
    const float*  nbg = neighbors + ((size_t)(b * C_) * N_ + (size_t)n) * K_ + kh * 8;
    const float4* WqT = (const float4*)sW;                    // [c][16] float4
    const float4* WkT = (const float4*)(sW + W_ELEMS);
    const float4* WvT = (const float4*)(sW + 2 * W_ELEMS);

    // ======== pass 1: q[j*4+dd] = q_{2hh+j}[kh*4+dd] (scale pre-folded) ====
    float q[8];
    #pragma unroll
    for (int d = 0; d < 8; d++) q[d] = 0.f;
    #pragma unroll 4
    for (int c = 0; c < CP3; c++) {
        float x = pcp[c];
        float4 w0 = WqT[c * 16 + wb];         // head 2hh,   dims kh*4..+3
        float4 w1 = WqT[c * 16 + 8 + wb];     // head 2hh+1, dims kh*4..+3
        q[0] = fmaf(w0.x, x, q[0]); q[1] = fmaf(w0.y, x, q[1]);
        q[2] = fmaf(w0.z, x, q[2]); q[3] = fmaf(w0.w, x, q[3]);
        q[4] = fmaf(w1.x, x, q[4]); q[5] = fmaf(w1.y, x, q[5]);
        q[6] = fmaf(w1.z, x, q[6]); q[7] = fmaf(w1.w, x, q[7]);
    }

    // ======== pass 2: energies e[j][k'] over own 8 k for 2 heads ========
    float e0[16];
    #pragma unroll
    for (int k = 0; k < 16; k++) e0[k] = 0.f;
    #pragma unroll 2
    for (int c = 0; c < C_; c++) {
        const float4* nr = (const float4*)(nbg + (size_t)c * CSTR);
        float4 na = nr[0], nbv = nr[1];
        float4 w0 = WkT[c * 16 + wb];
        float4 w1 = WkT[c * 16 + 8 + wb];
        float rp0 = fmaf(w0.x, q[0], w0.y * q[1]);
        float rp1 = fmaf(w1.x, q[4], w1.y * q[5]);
        rp0 = fmaf(w0.z, q[2], rp0); rp1 = fmaf(w1.z, q[6], rp1);
        rp0 = fmaf(w0.w, q[3], rp0); rp1 = fmaf(w1.w, q[7], rp1);
        float r0 = rp0 + __shfl_xor_sync(0xffffffffu, rp0, 4);
        float r1 = rp1 + __shfl_xor_sync(0xffffffffu, rp1, 4);
        e0[0]  = fmaf(r0, na.x, e0[0]);  e0[1]  = fmaf(r0, na.y, e0[1]);
        e0[2]  = fmaf(r0, na.z, e0[2]);  e0[3]  = fmaf(r0, na.w, e0[3]);
        e0[4]  = fmaf(r0, nbv.x, e0[4]); e0[5]  = fmaf(r0, nbv.y, e0[5]);
        e0[6]  = fmaf(r0, nbv.z, e0[6]); e0[7]  = fmaf(r0, nbv.w, e0[7]);
        e0[8]  = fmaf(r1, na.x, e0[8]);  e0[9]  = fmaf(r1, na.y, e0[9]);
        e0[10] = fmaf(r1, na.z, e0[10]); e0[11] = fmaf(r1, na.w, e0[11]);
        e0[12] = fmaf(r1, nbv.x, e0[12]); e0[13] = fmaf(r1, nbv.y, e0[13]);
        e0[14] = fmaf(r1, nbv.z, e0[14]); e0[15] = fmaf(r1, nbv.w, e0[15]);
    }
    #pragma unroll
    for (int j = 0; j < 3; j++) {             // xyz tail rows from smem
        int c = C_ + j;
        float4 na = sxp[j * 4], nbv = sxp[j * 4 + 1];
        float4 w0 = WkT[c * 16 + wb];
        float4 w1 = WkT[c * 16 + 8 + wb];
        float rp0 = fmaf(w0.x, q[0], w0.y * q[1]);
        float rp1 = fmaf(w1.x, q[4], w1.y * q[5]);
        rp0 = fmaf(w0.z, q[2], rp0); rp1 = fmaf(w1.z, q[6], rp1);
        rp0 = fmaf(w0.w, q[3], rp0); rp1 = fmaf(w1.w, q[7], rp1);
        float r0 = rp0 + __shfl_xor_sync(0xffffffffu, rp0, 4);
        float r1 = rp1 + __shfl_xor_sync(0xffffffffu, rp1, 4);
        e0[0]  = fmaf(r0, na.x, e0[0]);  e0[1]  = fmaf(r0, na.y, e0[1]);
        e0[2]  = fmaf(r0, na.z, e0[2]);  e0[3]  = fmaf(r0, na.w, e0[3]);
        e0[4]  = fmaf(r0, nbv.x, e0[4]); e0[5]  = fmaf(r0, nbv.y, e0[5]);
        e0[6]  = fmaf(r0, nbv.z, e0[6]); e0[7]  = fmaf(r0, nbv.w, e0[7]);
        e0[8]  = fmaf(r1, na.x, e0[8]);  e0[9]  = fmaf(r1, na.y, e0[9]);
        e0[10] = fmaf(r1, na.z, e0[10]); e0[11] = fmaf(r1, na.w, e0[11]);
        e0[12] = fmaf(r1, nbv.x, e0[12]); e0[13] = fmaf(r1, nbv.y, e0[13]);
        e0[14] = fmaf(r1, nbv.z, e0[14]); e0[15] = fmaf(r1, nbv.w, e0[15]);
    }

    // ======== softmax per head over 16 k (8 local + kh-partner) ========
    float m0 = e0[0], m1 = e0[8];
    #pragma unroll
    for (int k = 1; k < 8; k++) { m0 = fmaxf(m0, e0[k]); m1 = fmaxf(m1, e0[8 + k]); }
    m0 = fmaxf(m0, __shfl_xor_sync(0xffffffffu, m0, 4));
    m1 = fmaxf(m1, __shfl_xor_sync(0xffffffffu, m1, 4));
    float s0sum = 0.f, s1sum = 0.f;
    #pragma unroll
    for (int k = 0; k < 8; k++) {
        e0[k]     = __expf(e0[k] - m0);     s0sum += e0[k];
        e0[8 + k] = __expf(e0[8 + k] - m1); s1sum += e0[8 + k];
    }
    s0sum += __shfl_xor_sync(0xffffffffu, s0sum, 4);
    s1sum += __shfl_xor_sync(0xffffffffu, s1sum, 4);
    float inv0 = 1.f / s0sum, inv1 = 1.f / s1sum;
    #pragma unroll
    for (int k = 0; k < 8; k++) { e0[k] *= inv0; e0[8 + k] *= inv1; }

    // ======== pass 3: o[j*4+dd] += Wv[c, (2hh+j)*8+kh*4+dd] * s_j ========
    float o[8];
    #pragma unroll
    for (int d = 0; d < 8; d++) o[d] = 0.f;
    #pragma unroll 2
    for (int c = 0; c < C_; c++) {
        const float4* nr = (const float4*)(nbg + (size_t)c * CSTR);
        float4 na = nr[0], nbv = nr[1];
        float sa0 = fmaf(e0[0], na.x, e0[1] * na.y);
        float sb0 = fmaf(e0[2], na.z, e0[3] * na.w);
        float sa1 = fmaf(e0[8], na.x, e0[9] * na.y);
        float sb1 = fmaf(e0[10], na.z, e0[11] * na.w);
        sa0 = fmaf(e0[4], nbv.x, sa0); sb0 = fmaf(e0[5], nbv.y, sb0);
        sa1 = fmaf(e0[12], nbv.x, sa1); sb1 = fmaf(e0[13], nbv.y, sb1);
        sa0 = fmaf(e0[6], nbv.z, sa0); sb0 = fmaf(e0[7], nbv.w, sb0);
        sa1 = fmaf(e0[14], nbv.z, sa1); sb1 = fmaf(e0[15], nbv.w, sb1);
        float sp0 = sa0 + sb0, sp1 = sa1 + sb1;
        float s0 = sp0 + __shfl_xor_sync(0xffffffffu, sp0, 4);
        float s1 = sp1 + __shfl_xor_sync(0xffffffffu, sp1, 4);
        float4 w0 = WvT[c * 16 + wb];
        float4 w1 = WvT[c * 16 + 8 + wb];
        o[0] = fmaf(w0.x, s0, o[0]); o[1] = fmaf(w0.y, s0, o[1]);
        o[2] = fmaf(w0.z, s0, o[2]); o[3] = fmaf(w0.w, s0, o[3]);
        o[4] = fmaf(w1.x, s1, o[4]); o[5] = fmaf(w1.y, s1, o[5]);
        o[6] = fmaf(w1.z, s1, o[6]); o[7] = fmaf(w1.w, s1, o[7]);
    }
    #pragma unroll
    for (int j = 0; j < 3; j++) {
        int c = C_ + j;
        float4 na = sxp[j * 4], nbv = sxp[j * 4 + 1];
        float sa0 = fmaf(e0[0], na.x, e0[1] * na.y);
        float sb0 = fmaf(e0[2], na.z, e0[3] * na.w);
        float sa1 = fmaf(e0[8], na.x, e0[9] * na.y);
        float sb1 = fmaf(e0[10], na.z, e0[11] * na.w);
        sa0 = fmaf(e0[4], nbv.x, sa0); sb0 = fmaf(e0[5], nbv.y, sb0);
        sa1 = fmaf(e0[12], nbv.x, sa1); sb1 = fmaf(e0[13], nbv.y, sb1);
        sa0 = fmaf(e0[6], nbv.z, sa0); sb0 = fmaf(e0[7], nbv.w, sb0);
        sa1 = fmaf(e0[14], nbv.z, sa1); sb1 = fmaf(e0[15], nbv.w, sb1);
        float sp0 = sa0 + sb0, sp1 = sa1 + sb1;
        float s0 = sp0 + __shfl_xor_sync(0xffffffffu, sp0, 4);
        float s1 = sp1 + __shfl_xor_sync(0xffffffffu, sp1, 4);
        float4 w0 = WvT[c * 16 + wb];
        float4 w1 = WvT[c * 16 + 8 + wb];
        o[0] = fmaf(w0.x, s0, o[0]); o[1] = fmaf(w0.y, s0, o[1]);
        o[2] = fmaf(w0.z, s0, o[2]); o[3] = fmaf(w0.w, s0, o[3]);
        o[4] = fmaf(w1.x, s1, o[4]); o[5] = fmaf(w1.y, s1, o[5]);
        o[6] = fmaf(w1.z, s1, o[6]); o[7] = fmaf(w1.w, s1, o[7]);
    }

    // ---- store: out[b, (2hh+j)*8 + kh*4 + dd, n]
    {
        float* ob0 = out + ((size_t)(b * C_ + (2 * hh) * 8 + kh * 4)) * N_ + n;
        float* ob1 = out + ((size_t)(b * C_ + (2 * hh + 1) * 8 + kh * 4)) * N_ + n;
        #pragma unroll
        for (int dd = 0; dd < 4; dd++) {
            ob0[(size_t)dd * N_] = o[dd];
            ob1[(size_t)dd * N_] = o[4 + dd];
        }
    }
}

extern "C" void kernel_launch(void* const* d_in, const int* in_sizes, int n_in,
                              void* d_out, int out_size)
{
    (void)in_sizes; (void)n_in; (void)out_size;
    const float* pcd       = (const float*)d_in[0];
    const float* neighbors = (const float*)d_in[1];
    const float* xyz       = (const float*)d_in[2];
    const float* Wq        = (const float*)d_in[3];
    const float* Wk        = (const float*)d_in[4];
    const float* Wv        = (const float*)d_in[5];
    const int*   idx_all   = (const int*)d_in[6];
    float* out = (float*)d_out;

    permute_w_kernel<<<(W_ELEMS + 255) / 256, 256>>>(Wq, Wk, Wv);

    const int grid = (B_ * N_) / PTS;   // 2048
    pt_attn_kernel<<<grid, THREADS>>>(pcd, neighbors, xyz, idx_all, out);
}